// round 6
// baseline (speedup 1.0000x reference)
#include <cuda.h>
#include <cuda_runtime.h>
#include <cuda_bf16.h>
#include <cuda_fp16.h>
#include <cstdint>

// ============================================================================
// y[8192,4096] = mean(|W|) * (x[8192,4096] @ sign(W)[4096,4096]^T)
// Round 6: fp16 mma.sync GEMM, CTA 128x256, warp tile 64x64 (8 warps),
// 5-stage cp.async pipeline, ldmatrix fragment loads, scale in epilogue.
// ============================================================================

#define M_TOTAL 8192
#define N_TOTAL 4096
#define K_TOTAL 4096

#define CTA_M 128
#define CTA_N 256
#define K_STEP 32
#define NK (K_TOTAL / K_STEP)    // 128
#define STAGES 5

// SMEM per stage: A[128][32] fp16 rows padded to 80B, B[256][32] same
#define ROW_BYTES 80
#define OFF_A 0
#define OFF_B (128 * ROW_BYTES)                    // 10240
#define STAGE_BYTES ((128 + 256) * ROW_BYTES)      // 30720
#define SMEM_TOTAL (STAGES * STAGE_BYTES)          // 153600

// ---------------------------------------------------------------------------
// Device scratch (allocation-free rule: __device__ globals)
// ---------------------------------------------------------------------------
__device__ __align__(1024) __half g_Ah[(size_t)M_TOTAL * K_TOTAL];
__device__ __align__(1024) __half g_Bsign[(size_t)N_TOTAL * K_TOTAL];
__device__ float g_partials[1024];
__device__ float g_scale;

// ---------------------------------------------------------------------------
// PTX helpers
// ---------------------------------------------------------------------------
__device__ __forceinline__ uint32_t smem_to_u32(const void* p) {
    uint32_t a;
    asm("{ .reg .u64 t; cvta.to.shared.u64 t, %1; cvt.u32.u64 %0, t; }" : "=r"(a) : "l"(p));
    return a;
}

__device__ __forceinline__ void cp_async16(uint32_t dst, const void* src) {
    asm volatile("cp.async.cg.shared.global [%0], [%1], 16;" :: "r"(dst), "l"(src) : "memory");
}
__device__ __forceinline__ void cp_commit() {
    asm volatile("cp.async.commit_group;" ::: "memory");
}
template <int N>
__device__ __forceinline__ void cp_wait() {
    asm volatile("cp.async.wait_group %0;" :: "n"(N) : "memory");
}

__device__ __forceinline__ void ldmatrix_x4(uint32_t& r0, uint32_t& r1,
                                            uint32_t& r2, uint32_t& r3, uint32_t addr) {
    asm volatile("ldmatrix.sync.aligned.m8n8.x4.shared.b16 {%0,%1,%2,%3}, [%4];"
                 : "=r"(r0), "=r"(r1), "=r"(r2), "=r"(r3) : "r"(addr));
}

__device__ __forceinline__ void mma16816(float& d0, float& d1, float& d2, float& d3,
                                         uint32_t a0, uint32_t a1, uint32_t a2, uint32_t a3,
                                         uint32_t b0, uint32_t b1) {
    asm volatile(
        "mma.sync.aligned.m16n8k16.row.col.f32.f16.f16.f32 "
        "{%0,%1,%2,%3}, {%4,%5,%6,%7}, {%8,%9}, {%0,%1,%2,%3};"
        : "+f"(d0), "+f"(d1), "+f"(d2), "+f"(d3)
        : "r"(a0), "r"(a1), "r"(a2), "r"(a3), "r"(b0), "r"(b1));
}

// ---------------------------------------------------------------------------
// Prep kernel 1: binarize W -> fp16 sign AND partial |W| sums (deterministic)
// ---------------------------------------------------------------------------
__global__ void binarize_reduce_kernel(const float* __restrict__ W) {
    __shared__ float sdata[256];
    size_t base = (size_t)blockIdx.x * 16384;
    float s = 0.0f;
    for (int i = threadIdx.x; i < 16384; i += 256) {
        float w = W[base + i];
        s += fabsf(w);
        float sg = (w > 0.0f) ? 1.0f : ((w < 0.0f) ? -1.0f : 0.0f);
        g_Bsign[base + i] = __float2half(sg);
    }
    sdata[threadIdx.x] = s;
    __syncthreads();
    for (int off = 128; off > 0; off >>= 1) {
        if (threadIdx.x < off) sdata[threadIdx.x] += sdata[threadIdx.x + off];
        __syncthreads();
    }
    if (threadIdx.x == 0) g_partials[blockIdx.x] = sdata[0];
}

__global__ void finalize_scale_kernel() {
    __shared__ float sdata[256];
    int t = threadIdx.x;
    float s = 0.0f;
    #pragma unroll
    for (int i = 0; i < 4; i++) s += g_partials[t * 4 + i];
    sdata[t] = s;
    __syncthreads();
    for (int off = 128; off > 0; off >>= 1) {
        if (t < off) sdata[t] += sdata[t + off];
        __syncthreads();
    }
    if (t == 0) g_scale = sdata[0] * (1.0f / 16777216.0f);
}

// Prep kernel 3: x (fp32) -> fp16. 8388608 float4 vectors.
__global__ void convert_x_kernel(const float* __restrict__ x) {
    size_t i = (size_t)blockIdx.x * 256 + threadIdx.x;
    float4 v = reinterpret_cast<const float4*>(x)[i];
    ushort4 hv = make_ushort4(__half_as_ushort(__float2half_rn(v.x)),
                              __half_as_ushort(__float2half_rn(v.y)),
                              __half_as_ushort(__float2half_rn(v.z)),
                              __half_as_ushort(__float2half_rn(v.w)));
    reinterpret_cast<ushort4*>(g_Ah)[i] = hv;
}

// ---------------------------------------------------------------------------
// GEMM kernel: CTA 128x256, 8 warps (2M x 4N), warp tile 64x64
// ---------------------------------------------------------------------------
__global__ void __launch_bounds__(256, 1) gemm_kernel(float* __restrict__ out) {
    extern __shared__ __align__(128) char smem[];
    const uint32_t smem_base = smem_to_u32(smem);

    const int tid = threadIdx.x;
    const int lane = tid & 31;
    const int wid = tid >> 5;
    const int wm = wid & 1;       // 0..1  -> m offset wm*64
    const int wn = wid >> 1;      // 0..3  -> n offset wn*64
    const int ntile = blockIdx.x; // 0..15
    const int mtile = blockIdx.y; // 0..63

    // ---- cp.async: 1536 16B-chunks per stage (A: 0..511, B: 512..1535) ----
    const char* gsrc[6];
    uint32_t doff[6];
    #pragma unroll
    for (int r = 0; r < 6; r++) {
        int c = tid + 256 * r;
        if (c < 512) {
            int row = c >> 2, quad = c & 3;
            gsrc[r] = (const char*)g_Ah + (size_t)(mtile * 128 + row) * 8192 + quad * 16;
            doff[r] = (uint32_t)(OFF_A + row * ROW_BYTES + quad * 16);
        } else {
            int cb = c - 512;
            int row = cb >> 2, quad = cb & 3;
            gsrc[r] = (const char*)g_Bsign + (size_t)(ntile * 256 + row) * 8192 + quad * 16;
            doff[r] = (uint32_t)(OFF_B + row * ROW_BYTES + quad * 16);
        }
    }

    auto load_stage = [&](int s, int kt) {
        const uint32_t st = smem_base + s * STAGE_BYTES;
        const size_t kb = (size_t)kt * 64;   // 32 fp16 = 64 bytes
        #pragma unroll
        for (int r = 0; r < 6; r++) cp_async16(st + doff[r], gsrc[r] + kb);
        cp_commit();
    };

    // ---- ldmatrix per-lane base addresses ----
    const uint32_t aBase = OFF_A + (uint32_t)((wm * 64 + (lane & 15)) * ROW_BYTES)
                         + (uint32_t)((lane >> 4) * 16);
    const uint32_t bLaneRow = (uint32_t)((lane & 7) + ((lane >> 4) & 1) * 8);
    const uint32_t bLaneCol = (uint32_t)(((lane >> 3) & 1) * 16);
    const uint32_t bBase = OFF_B + (uint32_t)((wn * 64 + bLaneRow) * ROW_BYTES) + bLaneCol;

    float acc[4][8][4];
    #pragma unroll
    for (int i = 0; i < 4; i++)
        #pragma unroll
        for (int j = 0; j < 8; j++)
            #pragma unroll
            for (int r = 0; r < 4; r++) acc[i][j][r] = 0.0f;

    // ---- prologue ----
    #pragma unroll
    for (int s = 0; s < STAGES - 1; s++) load_stage(s, s);

    int stage = 0;

    // ---- main loop ----
    for (int kt = 0; kt < NK; kt++) {
        cp_wait<STAGES - 2>();
        __syncthreads();

        if (kt + STAGES - 1 < NK) load_stage((kt + STAGES - 1) % STAGES, kt + STAGES - 1);

        const uint32_t st = smem_base + stage * STAGE_BYTES;
        if (++stage == STAGES) stage = 0;

        #pragma unroll
        for (int kk = 0; kk < 2; kk++) {
            const uint32_t ko = (uint32_t)(kk * 32);   // k16 = 32 bytes
            // B fragments: 4 x ldmatrix.x4 covering n0..63 (8 n8-blocks)
            uint32_t bq[16];
            #pragma unroll
            for (int jb = 0; jb < 4; jb++) {
                ldmatrix_x4(bq[4 * jb], bq[4 * jb + 1], bq[4 * jb + 2], bq[4 * jb + 3],
                            st + bBase + (uint32_t)(jb * 16 * ROW_BYTES) + ko);
            }
            #pragma unroll
            for (int i = 0; i < 4; i++) {
                uint32_t a0, a1, a2, a3;
                ldmatrix_x4(a0, a1, a2, a3,
                            st + aBase + (uint32_t)(i * 16 * ROW_BYTES) + ko);
                #pragma unroll
                for (int j = 0; j < 8; j++) {
                    mma16816(acc[i][j][0], acc[i][j][1], acc[i][j][2], acc[i][j][3],
                             a0, a1, a2, a3, bq[2 * j], bq[2 * j + 1]);
                }
            }
        }
    }
    cp_wait<0>();

    // ---- epilogue: scale + store ----
    const float scl = g_scale;
    const int mbase = mtile * 128 + wm * 64 + (lane >> 2);
    const int nbase = ntile * 256 + wn * 64 + (lane & 3) * 2;
    #pragma unroll
    for (int i = 0; i < 4; i++) {
        const int r0 = mbase + i * 16;
        #pragma unroll
        for (int j = 0; j < 8; j++) {
            const int c = nbase + j * 8;
            float2 v0 = make_float2(acc[i][j][0] * scl, acc[i][j][1] * scl);
            float2 v1 = make_float2(acc[i][j][2] * scl, acc[i][j][3] * scl);
            *reinterpret_cast<float2*>(out + (size_t)r0 * N_TOTAL + c) = v0;
            *reinterpret_cast<float2*>(out + (size_t)(r0 + 8) * N_TOTAL + c) = v1;
        }
    }
}

// ---------------------------------------------------------------------------
// Host launch
// ---------------------------------------------------------------------------
extern "C" void kernel_launch(void* const* d_in, const int* in_sizes, int n_in,
                              void* d_out, int out_size) {
    const float* x = (const float*)d_in[0];
    const float* W = (const float*)d_in[1];
    float* out = (float*)d_out;

    cudaFuncSetAttribute(gemm_kernel, cudaFuncAttributeMaxDynamicSharedMemorySize,
                         SMEM_TOTAL);

    binarize_reduce_kernel<<<1024, 256>>>(W);
    finalize_scale_kernel<<<1, 256>>>();
    convert_x_kernel<<<32768, 256>>>(x);
    gemm_kernel<<<dim3(N_TOTAL / CTA_N, M_TOTAL / CTA_M, 1), 256, SMEM_TOTAL>>>(out);
}

// round 7
// speedup vs baseline: 1.0918x; 1.0918x over previous
#include <cuda.h>
#include <cuda_runtime.h>
#include <cuda_bf16.h>
#include <cuda_fp16.h>
#include <cstdint>

// ============================================================================
// y[8192,4096] = mean(|W|) * (x[8192,4096] @ sign(W)[4096,4096]^T)
// Round 7: fp16 mma.sync GEMM. CTA 128x256 with 512 threads (16 warps, 4x4
// grid, warp tile 32x64) -> 4 warps/SMSP latency hiding + halved gmem traffic.
// 5-stage cp.async pipeline, ldmatrix, scale in epilogue.
// ============================================================================

#define M_TOTAL 8192
#define N_TOTAL 4096
#define K_TOTAL 4096

#define CTA_M 128
#define CTA_N 256
#define K_STEP 32
#define NK (K_TOTAL / K_STEP)    // 128
#define STAGES 5

// SMEM per stage: A[128][32] fp16 rows padded to 80B, B[256][32] same
#define ROW_BYTES 80
#define OFF_A 0
#define OFF_B (128 * ROW_BYTES)                    // 10240
#define STAGE_BYTES ((128 + 256) * ROW_BYTES)      // 30720
#define SMEM_TOTAL (STAGES * STAGE_BYTES)          // 153600

// ---------------------------------------------------------------------------
// Device scratch (allocation-free rule: __device__ globals)
// ---------------------------------------------------------------------------
__device__ __align__(1024) __half g_Ah[(size_t)M_TOTAL * K_TOTAL];
__device__ __align__(1024) __half g_Bsign[(size_t)N_TOTAL * K_TOTAL];
__device__ float g_partials[1024];
__device__ float g_scale;

// ---------------------------------------------------------------------------
// PTX helpers
// ---------------------------------------------------------------------------
__device__ __forceinline__ uint32_t smem_to_u32(const void* p) {
    uint32_t a;
    asm("{ .reg .u64 t; cvta.to.shared.u64 t, %1; cvt.u32.u64 %0, t; }" : "=r"(a) : "l"(p));
    return a;
}

__device__ __forceinline__ void cp_async16(uint32_t dst, const void* src) {
    asm volatile("cp.async.cg.shared.global [%0], [%1], 16;" :: "r"(dst), "l"(src) : "memory");
}
__device__ __forceinline__ void cp_commit() {
    asm volatile("cp.async.commit_group;" ::: "memory");
}
template <int N>
__device__ __forceinline__ void cp_wait() {
    asm volatile("cp.async.wait_group %0;" :: "n"(N) : "memory");
}

__device__ __forceinline__ void ldmatrix_x4(uint32_t& r0, uint32_t& r1,
                                            uint32_t& r2, uint32_t& r3, uint32_t addr) {
    asm volatile("ldmatrix.sync.aligned.m8n8.x4.shared.b16 {%0,%1,%2,%3}, [%4];"
                 : "=r"(r0), "=r"(r1), "=r"(r2), "=r"(r3) : "r"(addr));
}

__device__ __forceinline__ void mma16816(float& d0, float& d1, float& d2, float& d3,
                                         uint32_t a0, uint32_t a1, uint32_t a2, uint32_t a3,
                                         uint32_t b0, uint32_t b1) {
    asm volatile(
        "mma.sync.aligned.m16n8k16.row.col.f32.f16.f16.f32 "
        "{%0,%1,%2,%3}, {%4,%5,%6,%7}, {%8,%9}, {%0,%1,%2,%3};"
        : "+f"(d0), "+f"(d1), "+f"(d2), "+f"(d3)
        : "r"(a0), "r"(a1), "r"(a2), "r"(a3), "r"(b0), "r"(b1));
}

// ---------------------------------------------------------------------------
// Prep kernel 1: binarize W -> fp16 sign AND partial |W| sums (deterministic)
// ---------------------------------------------------------------------------
__global__ void binarize_reduce_kernel(const float* __restrict__ W) {
    __shared__ float sdata[256];
    size_t base = (size_t)blockIdx.x * 16384;
    float s = 0.0f;
    for (int i = threadIdx.x; i < 16384; i += 256) {
        float w = W[base + i];
        s += fabsf(w);
        float sg = (w > 0.0f) ? 1.0f : ((w < 0.0f) ? -1.0f : 0.0f);
        g_Bsign[base + i] = __float2half(sg);
    }
    sdata[threadIdx.x] = s;
    __syncthreads();
    for (int off = 128; off > 0; off >>= 1) {
        if (threadIdx.x < off) sdata[threadIdx.x] += sdata[threadIdx.x + off];
        __syncthreads();
    }
    if (threadIdx.x == 0) g_partials[blockIdx.x] = sdata[0];
}

__global__ void finalize_scale_kernel() {
    __shared__ float sdata[256];
    int t = threadIdx.x;
    float s = 0.0f;
    #pragma unroll
    for (int i = 0; i < 4; i++) s += g_partials[t * 4 + i];
    sdata[t] = s;
    __syncthreads();
    for (int off = 128; off > 0; off >>= 1) {
        if (t < off) sdata[t] += sdata[t + off];
        __syncthreads();
    }
    if (t == 0) g_scale = sdata[0] * (1.0f / 16777216.0f);
}

// Prep kernel 3: x (fp32) -> fp16. 8388608 float4 vectors.
__global__ void convert_x_kernel(const float* __restrict__ x) {
    size_t i = (size_t)blockIdx.x * 256 + threadIdx.x;
    float4 v = reinterpret_cast<const float4*>(x)[i];
    ushort4 hv = make_ushort4(__half_as_ushort(__float2half_rn(v.x)),
                              __half_as_ushort(__float2half_rn(v.y)),
                              __half_as_ushort(__float2half_rn(v.z)),
                              __half_as_ushort(__float2half_rn(v.w)));
    reinterpret_cast<ushort4*>(g_Ah)[i] = hv;
}

// ---------------------------------------------------------------------------
// GEMM kernel: CTA 128x256, 512 threads = 16 warps (4M x 4N), warp tile 32x64
// ---------------------------------------------------------------------------
__global__ void __launch_bounds__(512, 1) gemm_kernel(float* __restrict__ out) {
    extern __shared__ __align__(128) char smem[];
    const uint32_t smem_base = smem_to_u32(smem);

    const int tid = threadIdx.x;
    const int lane = tid & 31;
    const int wid = tid >> 5;
    const int wm = wid & 3;       // 0..3  -> m offset wm*32
    const int wn = wid >> 2;      // 0..3  -> n offset wn*64
    const int ntile = blockIdx.x; // 0..15
    const int mtile = blockIdx.y; // 0..63

    // ---- cp.async: 1536 16B-chunks/stage; 512 threads x 3 chunks.
    // chunk r=0: A rows 0..127; r=1: B rows 0..127; r=2: B rows 128..255.
    const int crow = tid >> 2;            // 0..127
    const int cquad = tid & 3;            // 0..3
    const char* pA = (const char*)g_Ah +
                     (size_t)(mtile * 128 + crow) * 8192 + cquad * 16;
    const char* pB = (const char*)g_Bsign +
                     (size_t)(ntile * 256 + crow) * 8192 + cquad * 16;
    const uint32_t dA = (uint32_t)(OFF_A + crow * ROW_BYTES + cquad * 16);
    const uint32_t dB = (uint32_t)(OFF_B + crow * ROW_BYTES + cquad * 16);
    // second B chunk: +128 rows = +128*8192 bytes gmem, +128*80 bytes smem

    auto load_stage = [&](int s, int kt) {
        const uint32_t st = smem_base + s * STAGE_BYTES;
        const size_t kb = (size_t)kt * 64;   // 32 fp16 = 64 bytes
        cp_async16(st + dA, pA + kb);
        cp_async16(st + dB, pB + kb);
        cp_async16(st + dB + 128 * ROW_BYTES, pB + (size_t)128 * 8192 + kb);
        cp_commit();
    };

    // ---- ldmatrix per-lane base addresses ----
    const uint32_t aBase = OFF_A + (uint32_t)((wm * 32 + (lane & 15)) * ROW_BYTES)
                         + (uint32_t)((lane >> 4) * 16);
    const uint32_t bLaneRow = (uint32_t)((lane & 7) + ((lane >> 4) & 1) * 8);
    const uint32_t bLaneCol = (uint32_t)(((lane >> 3) & 1) * 16);
    const uint32_t bBase = OFF_B + (uint32_t)((wn * 64 + bLaneRow) * ROW_BYTES) + bLaneCol;

    float acc[2][8][4];
    #pragma unroll
    for (int i = 0; i < 2; i++)
        #pragma unroll
        for (int j = 0; j < 8; j++)
            #pragma unroll
            for (int r = 0; r < 4; r++) acc[i][j][r] = 0.0f;

    // ---- prologue ----
    #pragma unroll
    for (int s = 0; s < STAGES - 1; s++) load_stage(s, s);

    int stage = 0;

    // ---- main loop ----
    for (int kt = 0; kt < NK; kt++) {
        cp_wait<STAGES - 2>();
        __syncthreads();

        if (kt + STAGES - 1 < NK) load_stage((kt + STAGES - 1) % STAGES, kt + STAGES - 1);

        const uint32_t st = smem_base + stage * STAGE_BYTES;
        if (++stage == STAGES) stage = 0;

        // All fragment loads for the full kt (k32) issued up-front:
        // 12 ldmatrix.x4 -> 48 regs; MMAs below overlap the loads.
        uint32_t aq[2][2][4];   // [kk][i][reg]
        uint32_t bq[2][16];     // [kk][8 n8-blocks x 2]
        #pragma unroll
        for (int kk = 0; kk < 2; kk++) {
            const uint32_t ko = (uint32_t)(kk * 32);
            #pragma unroll
            for (int jb = 0; jb < 4; jb++)
                ldmatrix_x4(bq[kk][4 * jb], bq[kk][4 * jb + 1],
                            bq[kk][4 * jb + 2], bq[kk][4 * jb + 3],
                            st + bBase + (uint32_t)(jb * 16 * ROW_BYTES) + ko);
            #pragma unroll
            for (int i = 0; i < 2; i++)
                ldmatrix_x4(aq[kk][i][0], aq[kk][i][1], aq[kk][i][2], aq[kk][i][3],
                            st + aBase + (uint32_t)(i * 16 * ROW_BYTES) + ko);
        }
        #pragma unroll
        for (int kk = 0; kk < 2; kk++) {
            #pragma unroll
            for (int i = 0; i < 2; i++) {
                #pragma unroll
                for (int j = 0; j < 8; j++) {
                    mma16816(acc[i][j][0], acc[i][j][1], acc[i][j][2], acc[i][j][3],
                             aq[kk][i][0], aq[kk][i][1], aq[kk][i][2], aq[kk][i][3],
                             bq[kk][2 * j], bq[kk][2 * j + 1]);
                }
            }
        }
    }
    cp_wait<0>();

    // ---- epilogue: scale + store ----
    const float scl = g_scale;
    const int mbase = mtile * 128 + wm * 32 + (lane >> 2);
    const int nbase = ntile * 256 + wn * 64 + (lane & 3) * 2;
    #pragma unroll
    for (int i = 0; i < 2; i++) {
        const int r0 = mbase + i * 16;
        #pragma unroll
        for (int j = 0; j < 8; j++) {
            const int c = nbase + j * 8;
            float2 v0 = make_float2(acc[i][j][0] * scl, acc[i][j][1] * scl);
            float2 v1 = make_float2(acc[i][j][2] * scl, acc[i][j][3] * scl);
            *reinterpret_cast<float2*>(out + (size_t)r0 * N_TOTAL + c) = v0;
            *reinterpret_cast<float2*>(out + (size_t)(r0 + 8) * N_TOTAL + c) = v1;
        }
    }
}

// ---------------------------------------------------------------------------
// Host launch
// ---------------------------------------------------------------------------
extern "C" void kernel_launch(void* const* d_in, const int* in_sizes, int n_in,
                              void* d_out, int out_size) {
    const float* x = (const float*)d_in[0];
    const float* W = (const float*)d_in[1];
    float* out = (float*)d_out;

    cudaFuncSetAttribute(gemm_kernel, cudaFuncAttributeMaxDynamicSharedMemorySize,
                         SMEM_TOTAL);

    binarize_reduce_kernel<<<1024, 256>>>(W);
    finalize_scale_kernel<<<1, 256>>>();
    convert_x_kernel<<<32768, 256>>>(x);
    gemm_kernel<<<dim3(N_TOTAL / CTA_N, M_TOTAL / CTA_M, 1), 512, SMEM_TOTAL>>>(out);
}

// round 8
// speedup vs baseline: 1.4021x; 1.2842x over previous
#include <cuda.h>
#include <cuda_runtime.h>
#include <cuda_bf16.h>
#include <cuda_fp16.h>
#include <cstdint>

// ============================================================================
// y[8192,4096] = mean(|W|) * (x[8192,4096] @ sign(W)[4096,4096]^T)
// Round 8: fp16 mma.sync GEMM. R5 topology (CTA 128x128, 8 warps, warp 64x32,
// 2 CTAs/SM) + K_STEP=64, swizzled 128B rows, 3 stages -> half the syncs,
// bigger scheduling window.
// ============================================================================

#define M_TOTAL 8192
#define N_TOTAL 4096
#define K_TOTAL 4096

#define CTA_M 128
#define CTA_N 128
#define K_STEP 64
#define NKT (K_TOTAL / K_STEP)   // 64
#define STAGES 3

// SMEM per stage: A[128][64] fp16 (128B rows, XOR swizzle), B[128][64] same
#define OFF_A 0
#define OFF_B 16384
#define STAGE_BYTES 32768
#define SMEM_TOTAL (STAGES * STAGE_BYTES)   // 98304 -> 2 CTAs/SM

// ---------------------------------------------------------------------------
// Device scratch (allocation-free rule: __device__ globals)
// ---------------------------------------------------------------------------
__device__ __align__(1024) __half g_Ah[(size_t)M_TOTAL * K_TOTAL];
__device__ __align__(1024) __half g_Bsign[(size_t)N_TOTAL * K_TOTAL];
__device__ float g_partials[1024];
__device__ float g_scale;

// ---------------------------------------------------------------------------
// PTX helpers
// ---------------------------------------------------------------------------
__device__ __forceinline__ uint32_t smem_to_u32(const void* p) {
    uint32_t a;
    asm("{ .reg .u64 t; cvta.to.shared.u64 t, %1; cvt.u32.u64 %0, t; }" : "=r"(a) : "l"(p));
    return a;
}

__device__ __forceinline__ void cp_async16(uint32_t dst, const void* src) {
    asm volatile("cp.async.cg.shared.global [%0], [%1], 16;" :: "r"(dst), "l"(src) : "memory");
}
__device__ __forceinline__ void cp_commit() {
    asm volatile("cp.async.commit_group;" ::: "memory");
}
template <int N>
__device__ __forceinline__ void cp_wait() {
    asm volatile("cp.async.wait_group %0;" :: "n"(N) : "memory");
}

__device__ __forceinline__ void ldmatrix_x4(uint32_t& r0, uint32_t& r1,
                                            uint32_t& r2, uint32_t& r3, uint32_t addr) {
    asm volatile("ldmatrix.sync.aligned.m8n8.x4.shared.b16 {%0,%1,%2,%3}, [%4];"
                 : "=r"(r0), "=r"(r1), "=r"(r2), "=r"(r3) : "r"(addr));
}

__device__ __forceinline__ void mma16816(float& d0, float& d1, float& d2, float& d3,
                                         uint32_t a0, uint32_t a1, uint32_t a2, uint32_t a3,
                                         uint32_t b0, uint32_t b1) {
    asm volatile(
        "mma.sync.aligned.m16n8k16.row.col.f32.f16.f16.f32 "
        "{%0,%1,%2,%3}, {%4,%5,%6,%7}, {%8,%9}, {%0,%1,%2,%3};"
        : "+f"(d0), "+f"(d1), "+f"(d2), "+f"(d3)
        : "r"(a0), "r"(a1), "r"(a2), "r"(a3), "r"(b0), "r"(b1));
}

// ---------------------------------------------------------------------------
// Prep kernels
// ---------------------------------------------------------------------------
__global__ void binarize_reduce_kernel(const float* __restrict__ W) {
    __shared__ float sdata[256];
    size_t base = (size_t)blockIdx.x * 16384;
    float s = 0.0f;
    for (int i = threadIdx.x; i < 16384; i += 256) {
        float w = W[base + i];
        s += fabsf(w);
        float sg = (w > 0.0f) ? 1.0f : ((w < 0.0f) ? -1.0f : 0.0f);
        g_Bsign[base + i] = __float2half(sg);
    }
    sdata[threadIdx.x] = s;
    __syncthreads();
    for (int off = 128; off > 0; off >>= 1) {
        if (threadIdx.x < off) sdata[threadIdx.x] += sdata[threadIdx.x + off];
        __syncthreads();
    }
    if (threadIdx.x == 0) g_partials[blockIdx.x] = sdata[0];
}

__global__ void finalize_scale_kernel() {
    __shared__ float sdata[256];
    int t = threadIdx.x;
    float s = 0.0f;
    #pragma unroll
    for (int i = 0; i < 4; i++) s += g_partials[t * 4 + i];
    sdata[t] = s;
    __syncthreads();
    for (int off = 128; off > 0; off >>= 1) {
        if (t < off) sdata[t] += sdata[t + off];
        __syncthreads();
    }
    if (t == 0) g_scale = sdata[0] * (1.0f / 16777216.0f);
}

__global__ void convert_x_kernel(const float* __restrict__ x) {
    size_t i = (size_t)blockIdx.x * 256 + threadIdx.x;
    float4 v = reinterpret_cast<const float4*>(x)[i];
    ushort4 hv = make_ushort4(__half_as_ushort(__float2half_rn(v.x)),
                              __half_as_ushort(__float2half_rn(v.y)),
                              __half_as_ushort(__float2half_rn(v.z)),
                              __half_as_ushort(__float2half_rn(v.w)));
    reinterpret_cast<ushort4*>(g_Ah)[i] = hv;
}

// ---------------------------------------------------------------------------
// GEMM kernel: CTA 128x128, 8 warps (2M x 4N), warp tile 64x32, K_STEP 64
// SMEM rows: 128 bytes; 16B-chunk c of row r stored at chunk (c ^ (r&7)).
// ---------------------------------------------------------------------------
__global__ void __launch_bounds__(256, 2) gemm_kernel(float* __restrict__ out) {
    extern __shared__ __align__(128) char smem[];
    const uint32_t smem_base = smem_to_u32(smem);

    const int tid = threadIdx.x;
    const int lane = tid & 31;
    const int wid = tid >> 5;
    const int wm = wid & 1;       // 0..1  -> m offset wm*64
    const int wn = wid >> 1;      // 0..3  -> n offset wn*32
    const int ntile = blockIdx.x; // 0..31
    const int mtile = blockIdx.y; // 0..63

    // ---- cp.async mapping: per stage 2048 chunks (A 1024 + B 1024).
    // Thread t handles chunk column c = t&7 of rows (t>>3) + 32*i, i=0..3,
    // in BOTH tiles. Swizzled chunk = c ^ (row&7); row&7 invariant in i.
    const int cquad = tid & 7;            // 16B chunk within row
    const int row0 = tid >> 3;            // 0..31
    const uint32_t csw16 = (uint32_t)((cquad ^ (row0 & 7)) * 16);
    const char* pA = (const char*)g_Ah +
                     (size_t)(mtile * 128 + row0) * 8192 + cquad * 16;
    const char* pB = (const char*)g_Bsign +
                     (size_t)(ntile * 128 + row0) * 8192 + cquad * 16;
    const uint32_t dA = (uint32_t)(OFF_A + row0 * 128) + csw16;
    const uint32_t dB = (uint32_t)(OFF_B + row0 * 128) + csw16;

    auto load_stage = [&](int s, int kt) {
        const uint32_t st = smem_base + s * STAGE_BYTES;
        const size_t kb = (size_t)kt * 128;   // 64 fp16 = 128 bytes
        #pragma unroll
        for (int i = 0; i < 4; i++)
            cp_async16(st + dA + i * 32 * 128, pA + (size_t)i * 32 * 8192 + kb);
        #pragma unroll
        for (int i = 0; i < 4; i++)
            cp_async16(st + dB + i * 32 * 128, pB + (size_t)i * 32 * 8192 + kb);
        cp_commit();
    };

    // ---- ldmatrix per-lane addressing ----
    // row&7 == lane&7 for every fragment row below (all row bases are mult of 8),
    // so swizzled chunk = (c_lin ^ (lane&7)).
    const uint32_t lo7 = (uint32_t)(lane & 7);
    const uint32_t aHi = (uint32_t)(lane >> 4);          // 0/1 -> k8-15 half
    const uint32_t bHi = (uint32_t)((lane >> 3) & 1);    // 0/1 -> k8-15 half
    uint32_t aRowOff[4];
    #pragma unroll
    for (int i = 0; i < 4; i++)
        aRowOff[i] = (uint32_t)(OFF_A + (wm * 64 + i * 16 + (lane & 15)) * 128);
    uint32_t bRowOff[2];
    #pragma unroll
    for (int j2 = 0; j2 < 2; j2++)
        bRowOff[j2] = (uint32_t)(OFF_B + (wn * 32 + (lane & 7) +
                                          ((lane >> 4) & 1) * 8 + j2 * 16) * 128);

    float acc[4][4][4];
    #pragma unroll
    for (int i = 0; i < 4; i++)
        #pragma unroll
        for (int j = 0; j < 4; j++)
            #pragma unroll
            for (int r = 0; r < 4; r++) acc[i][j][r] = 0.0f;

    // ---- prologue ----
    #pragma unroll
    for (int s = 0; s < STAGES - 1; s++) load_stage(s, s);

    int stage = 0;

    // ---- main loop: 64 iterations, one sync each ----
    for (int kt = 0; kt < NKT; kt++) {
        cp_wait<STAGES - 2>();
        __syncthreads();

        if (kt + STAGES - 1 < NKT) load_stage((kt + STAGES - 1) % STAGES, kt + STAGES - 1);

        const uint32_t st = smem_base + stage * STAGE_BYTES;
        if (++stage == STAGES) stage = 0;

        #pragma unroll
        for (int kk = 0; kk < 4; kk++) {
            const uint32_t aC = ((uint32_t)(kk * 2) + aHi) ^ lo7;
            const uint32_t bC = ((uint32_t)(kk * 2) + bHi) ^ lo7;
            uint32_t bq[8];
            #pragma unroll
            for (int j2 = 0; j2 < 2; j2++)
                ldmatrix_x4(bq[4 * j2], bq[4 * j2 + 1], bq[4 * j2 + 2], bq[4 * j2 + 3],
                            st + bRowOff[j2] + bC * 16);
            #pragma unroll
            for (int i = 0; i < 4; i++) {
                uint32_t a0, a1, a2, a3;
                ldmatrix_x4(a0, a1, a2, a3, st + aRowOff[i] + aC * 16);
                #pragma unroll
                for (int j = 0; j < 4; j++) {
                    mma16816(acc[i][j][0], acc[i][j][1], acc[i][j][2], acc[i][j][3],
                             a0, a1, a2, a3, bq[2 * j], bq[2 * j + 1]);
                }
            }
        }
    }
    cp_wait<0>();

    // ---- epilogue: scale + store ----
    const float scl = g_scale;
    const int mbase = mtile * 128 + wm * 64 + (lane >> 2);
    const int nbase = ntile * 128 + wn * 32 + (lane & 3) * 2;
    #pragma unroll
    for (int i = 0; i < 4; i++) {
        const int r0 = mbase + i * 16;
        #pragma unroll
        for (int j = 0; j < 4; j++) {
            const int c = nbase + j * 8;
            float2 v0 = make_float2(acc[i][j][0] * scl, acc[i][j][1] * scl);
            float2 v1 = make_float2(acc[i][j][2] * scl, acc[i][j][3] * scl);
            *reinterpret_cast<float2*>(out + (size_t)r0 * N_TOTAL + c) = v0;
            *reinterpret_cast<float2*>(out + (size_t)(r0 + 8) * N_TOTAL + c) = v1;
        }
    }
}

// ---------------------------------------------------------------------------
// Host launch
// ---------------------------------------------------------------------------
extern "C" void kernel_launch(void* const* d_in, const int* in_sizes, int n_in,
                              void* d_out, int out_size) {
    const float* x = (const float*)d_in[0];
    const float* W = (const float*)d_in[1];
    float* out = (float*)d_out;

    cudaFuncSetAttribute(gemm_kernel, cudaFuncAttributeMaxDynamicSharedMemorySize,
                         SMEM_TOTAL);

    binarize_reduce_kernel<<<1024, 256>>>(W);
    finalize_scale_kernel<<<1, 256>>>();
    convert_x_kernel<<<32768, 256>>>(x);
    gemm_kernel<<<dim3(N_TOTAL / CTA_N, M_TOTAL / CTA_M, 1), 256, SMEM_TOTAL>>>(out);
}